// round 9
// baseline (speedup 1.0000x reference)
#include <cuda_runtime.h>
#include <cuda_fp16.h>
#include <math.h>

#define BV   8
#define CCH  47
#define CPH  48          // padded half-channels per pixel (96B)
#define FHH  60
#define FWW  80
#define DHH  240
#define DWW  320
#define NPTS 150000
#define WPB  8           // warps (points) per block in fuse

// Scratch (no allocations allowed)
__device__ float g_proj[BV][24];
__device__ __align__(16) __half g_feats_h[BV * FHH * FWW * CPH];

// ---------------------------------------------------------------------------
// Float Gauss-Jordan pose inverse (matches reference f32 inverse; exact for
// these I+translation poses) + stash K rows unfused.
// ---------------------------------------------------------------------------
__device__ void prep_view(int v, const float* __restrict__ poses,
                          const float* __restrict__ Kc,
                          const float* __restrict__ Kd) {
    float a[4][8];
    for (int i = 0; i < 4; i++)
        for (int j = 0; j < 4; j++) {
            a[i][j]     = poses[v * 16 + i * 4 + j];
            a[i][4 + j] = (i == j) ? 1.0f : 0.0f;
        }
    for (int col = 0; col < 4; col++) {
        int piv = col;
        float best = fabsf(a[col][col]);
        for (int r = col + 1; r < 4; r++) {
            float m = fabsf(a[r][col]);
            if (m > best) { best = m; piv = r; }
        }
        if (piv != col)
            for (int j = 0; j < 8; j++) {
                float t = a[col][j]; a[col][j] = a[piv][j]; a[piv][j] = t;
            }
        float inv = 1.0f / a[col][col];
        for (int j = 0; j < 8; j++) a[col][j] *= inv;
        for (int r = 0; r < 4; r++) {
            if (r == col) continue;
            float f = a[r][col];
            for (int j = 0; j < 8; j++) a[r][j] -= f * a[col][j];
        }
    }
    float* o = g_proj[v];
    for (int i = 0; i < 3; i++)
        for (int j = 0; j < 4; j++)
            o[i * 4 + j] = a[i][4 + j];
    for (int j = 0; j < 3; j++) o[12 + j] = Kc[v * 9 + 0 + j];
    for (int j = 0; j < 3; j++) o[15 + j] = Kc[v * 9 + 3 + j];
    for (int j = 0; j < 3; j++) o[18 + j] = Kd[v * 9 + 0 + j];
    for (int j = 0; j < 3; j++) o[21 + j] = Kd[v * 9 + 3 + j];
}

// ---------------------------------------------------------------------------
// Transpose+convert (V,C,H,W) f32 -> (V,H,W,Cpad) f16, via smem.
// Block per (v,y). Block 0 threads 0-7 also run pose prep.
// ---------------------------------------------------------------------------
__global__ void __launch_bounds__(256)
transpose_feats_kernel(const float* __restrict__ feats,
                       const float* __restrict__ poses,
                       const float* __restrict__ Kc,
                       const float* __restrict__ Kd) {
    __shared__ float tile[CCH * 81];
    const int bid = blockIdx.x;               // 0..479
    const int v = bid / FHH;
    const int y = bid % FHH;
    const int tid = threadIdx.x;

    for (int i = tid; i < CCH * FWW; i += 256) {
        int c = i / FWW, x = i % FWW;
        tile[c * 81 + x] = feats[((v * CCH + c) * FHH + y) * FWW + x];
    }
    __syncthreads();

    __half2* ob = reinterpret_cast<__half2*>(
        g_feats_h + ((size_t)v * FHH * FWW + (size_t)y * FWW) * CPH);
    for (int i = tid; i < FWW * (CPH / 2); i += 256) {
        int x = i / (CPH / 2), cw = i % (CPH / 2);
        int c0 = 2 * cw, c1 = 2 * cw + 1;
        float a = tile[c0 * 81 + x];
        float b = (c1 < CCH) ? tile[c1 * 81 + x] : 0.0f;
        ob[i] = __halves2half2(__float2half_rn(a), __float2half_rn(b));
    }

    if (bid == 0 && tid < BV)
        prep_view(tid, poses, Kc, Kd);
}

// Frozen rounding recipe (matches XLA): unfused mul-then-reduce dots.
__device__ __forceinline__ float dot4_mr(const float* r, float x, float y,
                                         float z, float w) {
    float t0 = __fmul_rn(r[0], x);
    float t1 = __fmul_rn(r[1], y);
    float t2 = __fmul_rn(r[2], z);
    float t3 = __fmul_rn(r[3], w);
    return __fadd_rn(__fadd_rn(__fadd_rn(t0, t1), t2), t3);
}
__device__ __forceinline__ float dot3_mr(const float* r, float x, float y,
                                         float z) {
    float t0 = __fmul_rn(r[0], x);
    float t1 = __fmul_rn(r[1], y);
    float t2 = __fmul_rn(r[2], z);
    return __fadd_rn(__fadd_rn(t0, t1), t2);
}

// ---------------------------------------------------------------------------
// Fuse: one WARP per point. Lane l projects view (l&7) with the frozen math.
// Gather lane roles (lanes 0-23): row = lane&1, corner = (lane>>1)&1,
// slot = lane>>2 (6 slots x 8 halfs). Folds: xor1 (row), xor2 (corner) —
// power-of-2 strides, lanes%4==0 hold full sums.
// ---------------------------------------------------------------------------
__global__ void __launch_bounds__(256)
fuse_kernel(const float* __restrict__ coords,
            const float* __restrict__ depth,
            float* __restrict__ out) {
    const unsigned FULL = 0xffffffffu;
    const int warp = threadIdx.x >> 5;
    const int lane = threadIdx.x & 31;
    const int n = blockIdx.x * WPB + warp;

    const float px = coords[n * 3 + 0];
    const float py = coords[n * 3 + 1];
    const float pz = coords[n * 3 + 2];

    // ---- projection for view (lane & 7) — EXACT frozen recipe ----
    const int v = lane & 7;
    const float* P = g_proj[v];
    float cam0 = dot4_mr(P + 0, px, py, pz, 1.0f);
    float cam1 = dot4_mr(P + 4, px, py, pz, 1.0f);
    float cam2 = dot4_mr(P + 8, px, py, pz, 1.0f);
    float z  = cam2;
    float zs = (fabsf(z) > 1e-6f) ? z : 1e-6f;
    float recip = __fdiv_rn(1.0f, zs);

    float uc = __fmul_rn(dot3_mr(P + 12, cam0, cam1, cam2), recip);
    float vc = __fmul_rn(dot3_mr(P + 15, cam0, cam1, cam2), recip);
    float ud = __fmul_rn(dot3_mr(P + 18, cam0, cam1, cam2), recip);
    float vd = __fmul_rn(dot3_mr(P + 21, cam0, cam1, cam2), recip);

    bool valid_c = (uc >= 0.0f) & (uc <= (float)(FWW - 1)) &
                   (vc >= 0.0f) & (vc <= (float)(FHH - 1));
    bool valid_d = (ud >= 0.0f) & (ud <= (float)(DWW - 1)) &
                   (vd >= 0.0f) & (vd <= (float)(DHH - 1));

    int xi = (int)fminf(fmaxf(rintf(ud), 0.0f), (float)(DWW - 1));
    int yi = (int)fminf(fmaxf(rintf(vd), 0.0f), (float)(DHH - 1));
    float ds = __ldg(&depth[(v * DHH + yi) * DWW + xi]);

    bool valid = valid_c & valid_d & (z > 0.0f) & (ds > 0.0f);
    float dist = __fmul_rn(fabsf(__fsub_rn(z, ds)), 16.0f);
    float w  = valid ? expf(-__fmul_rn(dist, dist)) : 0.0f;
    float vc01 = valid ? 1.0f : 0.0f;

    // wsum/cnt: xor-butterfly within each 8-lane view group
    float wsum = w, cnt = vc01;
#pragma unroll
    for (int d = 1; d < 8; d <<= 1) {
        wsum += __shfl_xor_sync(FULL, wsum, d);
        cnt  += __shfl_xor_sync(FULL, cnt, d);
    }

    // per-view bilinear precompute (this lane's view; exact index math)
    float ucl = fminf(fmaxf(uc, 0.0f), (float)(FWW - 1));
    float vcl = fminf(fmaxf(vc, 0.0f), (float)(FHH - 1));
    float x0f = floorf(ucl), y0f = floorf(vcl);
    int x0 = (int)x0f, y0 = (int)y0f;
    int x1 = min(x0 + 1, FWW - 1);
    int y1 = min(y0 + 1, FHH - 1);
    float wx = ucl - x0f, wy = vcl - y0f;
    float wq0 = w * (1.0f - wx);       // corner x0 weight (pre-row)
    float wq1 = w * wx;                // corner x1 weight (pre-row)
    int addr00 = (y0 * FWW + x0) * CPH;         // half units
    int dxo = (x1 - x0) * CPH;
    int dyo = (y1 - y0) * FWW * CPH;

    unsigned mask = __ballot_sync(FULL, w != 0.0f) & 0xffu;

    // gather lane roles (power-of-2 fold strides)
    const int row    = lane & 1;
    const int corner = (lane >> 1) & 1;
    const int slot   = lane >> 2;            // 0..5 active
    const bool ld_act = (lane < 24);
    float acc[8];
#pragma unroll
    for (int j = 0; j < 8; j++) acc[j] = 0.0f;

    while (mask) {
        int vv = __ffs(mask) - 1;
        mask &= mask - 1;
        float q0  = __shfl_sync(FULL, wq0, vv);
        float q1  = __shfl_sync(FULL, wq1, vv);
        float wyv = __shfl_sync(FULL, wy, vv);
        int a00   = __shfl_sync(FULL, addr00, vv);
        int dxv   = __shfl_sync(FULL, dxo, vv);
        int dyv   = __shfl_sync(FULL, dyo, vv);
        float wA = (corner ? q1 : q0) * (row ? wyv : (1.0f - wyv));
        if (ld_act) {
            const __half* hp = g_feats_h + (size_t)vv * (FHH * FWW * CPH)
                             + a00 + corner * dxv + row * dyv + slot * 8;
            uint4 raw = __ldg(reinterpret_cast<const uint4*>(hp));
            const __half2* h2 = reinterpret_cast<const __half2*>(&raw);
#pragma unroll
            for (int j = 0; j < 4; j++) {
                float2 f = __half22float2(h2[j]);
                acc[2 * j + 0] = fmaf(wA, f.x, acc[2 * j + 0]);
                acc[2 * j + 1] = fmaf(wA, f.y, acc[2 * j + 1]);
            }
        }
    }

    // fold rows (xor 1), then corners (xor 2) — lanes %4==0 hold full sums
#pragma unroll
    for (int j = 0; j < 8; j++)
        acc[j] += __shfl_xor_sync(FULL, acc[j], 1);
#pragma unroll
    for (int j = 0; j < 8; j++)
        acc[j] += __shfl_xor_sync(FULL, acc[j], 2);

    __shared__ float sred[WPB][50];
    if (ld_act && (lane & 3) == 0) {
#pragma unroll
        for (int j = 0; j < 8; j++)
            sred[warp][slot * 8 + j] = acc[j];
    }
    __syncwarp();
    if (lane == 0) {
        sred[warp][47] = wsum;   // overwrite padding channel
        sred[warp][48] = cnt;
    }
    __syncthreads();

    // coalesced block-wide store: out = density(47,N) | wsum(N) | cnt(N)
    const int base_n = blockIdx.x * WPB;
    for (int t = threadIdx.x; t < 49 * WPB; t += 256) {
        int c = t >> 3, j = t & 7;
        out[(size_t)c * NPTS + base_n + j] = sred[j][c];
    }
}

// ---------------------------------------------------------------------------
extern "C" void kernel_launch(void* const* d_in, const int* in_sizes, int n_in,
                              void* d_out, int out_size) {
    const float* img_feats  = (const float*)d_in[0];   // (1,8,47,60,80)
    const float* pred_depth = (const float*)d_in[1];   // (1,8,240,320)
    const float* poses      = (const float*)d_in[2];   // (1,8,4,4)
    const float* K_color    = (const float*)d_in[3];   // (1,8,3,3)
    const float* K_depth    = (const float*)d_in[4];   // (1,8,3,3)
    const float* coords     = (const float*)d_in[5];   // (1,150000,3)
    float* out = (float*)d_out;

    transpose_feats_kernel<<<BV * FHH, 256>>>(img_feats, poses, K_color, K_depth);
    fuse_kernel<<<NPTS / WPB, 256>>>(coords, pred_depth, out);
}

// round 14
// speedup vs baseline: 1.8655x; 1.8655x over previous
#include <cuda_runtime.h>
#include <cuda_fp16.h>
#include <math.h>

#define BV   8
#define CCH  47
#define CPH  64          // padded half-channels per pixel (128B, line-aligned)
#define FHH  60
#define FWW  80
#define DHH  240
#define DWW  320
#define NPTS 150000
#define PPB  32          // points per block (8 warps x 4 points)

// Scratch (no allocations allowed)
__device__ float g_proj[BV][24];
__device__ __align__(16) __half g_feats_h[BV * FHH * FWW * CPH];

// ---------------------------------------------------------------------------
// Float Gauss-Jordan pose inverse (matches reference f32 inverse; exact for
// these I+translation poses) + stash K rows unfused.
// ---------------------------------------------------------------------------
__device__ void prep_view(int v, const float* __restrict__ poses,
                          const float* __restrict__ Kc,
                          const float* __restrict__ Kd) {
    float a[4][8];
    for (int i = 0; i < 4; i++)
        for (int j = 0; j < 4; j++) {
            a[i][j]     = poses[v * 16 + i * 4 + j];
            a[i][4 + j] = (i == j) ? 1.0f : 0.0f;
        }
    for (int col = 0; col < 4; col++) {
        int piv = col;
        float best = fabsf(a[col][col]);
        for (int r = col + 1; r < 4; r++) {
            float m = fabsf(a[r][col]);
            if (m > best) { best = m; piv = r; }
        }
        if (piv != col)
            for (int j = 0; j < 8; j++) {
                float t = a[col][j]; a[col][j] = a[piv][j]; a[piv][j] = t;
            }
        float inv = 1.0f / a[col][col];
        for (int j = 0; j < 8; j++) a[col][j] *= inv;
        for (int r = 0; r < 4; r++) {
            if (r == col) continue;
            float f = a[r][col];
            for (int j = 0; j < 8; j++) a[r][j] -= f * a[col][j];
        }
    }
    float* o = g_proj[v];
    for (int i = 0; i < 3; i++)
        for (int j = 0; j < 4; j++)
            o[i * 4 + j] = a[i][4 + j];
    for (int j = 0; j < 3; j++) o[12 + j] = Kc[v * 9 + 0 + j];
    for (int j = 0; j < 3; j++) o[15 + j] = Kc[v * 9 + 3 + j];
    for (int j = 0; j < 3; j++) o[18 + j] = Kd[v * 9 + 0 + j];
    for (int j = 0; j < 3; j++) o[21 + j] = Kd[v * 9 + 3 + j];
}

// ---------------------------------------------------------------------------
// Transpose+convert (V,C,H,W) f32 -> (V,H,W,64) f16 via smem.
// Block per (v,y). Block 0 threads 0-7 also run pose prep.
// ---------------------------------------------------------------------------
__global__ void __launch_bounds__(256)
transpose_feats_kernel(const float* __restrict__ feats,
                       const float* __restrict__ poses,
                       const float* __restrict__ Kc,
                       const float* __restrict__ Kd) {
    __shared__ float tile[CCH * 81];
    const int bid = blockIdx.x;               // 0..479
    const int v = bid / FHH;
    const int y = bid % FHH;
    const int tid = threadIdx.x;

    for (int i = tid; i < CCH * FWW; i += 256) {
        int c = i / FWW, x = i % FWW;
        tile[c * 81 + x] = feats[((v * CCH + c) * FHH + y) * FWW + x];
    }
    __syncthreads();

    __half2* ob = reinterpret_cast<__half2*>(
        g_feats_h + ((size_t)v * FHH * FWW + (size_t)y * FWW) * CPH);
    for (int i = tid; i < FWW * (CPH / 2); i += 256) {
        int x = i / (CPH / 2), cw = i % (CPH / 2);
        int c0 = 2 * cw, c1 = 2 * cw + 1;
        float a = (c0 < CCH) ? tile[c0 * 81 + x] : 0.0f;
        float b = (c1 < CCH) ? tile[c1 * 81 + x] : 0.0f;
        ob[i] = __halves2half2(__float2half_rn(a), __float2half_rn(b));
    }

    if (bid == 0 && tid < BV)
        prep_view(tid, poses, Kc, Kd);
}

// Frozen rounding recipe (matches XLA): unfused mul-then-reduce dots.
__device__ __forceinline__ float dot4_mr(const float* r, float x, float y,
                                         float z, float w) {
    float t0 = __fmul_rn(r[0], x);
    float t1 = __fmul_rn(r[1], y);
    float t2 = __fmul_rn(r[2], z);
    float t3 = __fmul_rn(r[3], w);
    return __fadd_rn(__fadd_rn(__fadd_rn(t0, t1), t2), t3);
}
__device__ __forceinline__ float dot3_mr(const float* r, float x, float y,
                                         float z) {
    float t0 = __fmul_rn(r[0], x);
    float t1 = __fmul_rn(r[1], y);
    float t2 = __fmul_rn(r[2], z);
    return __fadd_rn(__fadd_rn(t0, t1), t2);
}

// ---------------------------------------------------------------------------
// Fuse: one warp = 4 POINTS. Lane role: (pt = lane>>3, view = lane&7) for
// projection; gather: each 8-lane group handles its point, lane = channel
// slot (8 halfs), loads all 4 corners itself (4 aligned 128B lines), fp32
// in-lane accumulation -> NO cross-lane channel folds.
// ---------------------------------------------------------------------------
__global__ void __launch_bounds__(256)
fuse_kernel(const float* __restrict__ coords,
            const float* __restrict__ depth,
            float* __restrict__ out) {
    const unsigned FULL = 0xffffffffu;
    const int tid  = threadIdx.x;
    const int wid  = tid >> 5;
    const int lane = tid & 31;
    const int grp  = lane >> 3;               // point sub-group 0..3
    const int slot = lane & 7;                // view id (proj) / channel slot
    const int pt_local = wid * 4 + grp;       // 0..31
    const int n  = blockIdx.x * PPB + pt_local;
    const int nL = (n < NPTS) ? n : (NPTS - 1);

    const float px = coords[nL * 3 + 0];
    const float py = coords[nL * 3 + 1];
    const float pz = coords[nL * 3 + 2];

    // ---- projection for view `slot` of point `pt` — EXACT frozen recipe ----
    const float* P = g_proj[slot];
    float cam0 = dot4_mr(P + 0, px, py, pz, 1.0f);
    float cam1 = dot4_mr(P + 4, px, py, pz, 1.0f);
    float cam2 = dot4_mr(P + 8, px, py, pz, 1.0f);
    float z  = cam2;
    float zs = (fabsf(z) > 1e-6f) ? z : 1e-6f;
    float recip = __fdiv_rn(1.0f, zs);

    float uc = __fmul_rn(dot3_mr(P + 12, cam0, cam1, cam2), recip);
    float vc = __fmul_rn(dot3_mr(P + 15, cam0, cam1, cam2), recip);
    float ud = __fmul_rn(dot3_mr(P + 18, cam0, cam1, cam2), recip);
    float vd = __fmul_rn(dot3_mr(P + 21, cam0, cam1, cam2), recip);

    bool valid_c = (uc >= 0.0f) & (uc <= (float)(FWW - 1)) &
                   (vc >= 0.0f) & (vc <= (float)(FHH - 1));
    bool valid_d = (ud >= 0.0f) & (ud <= (float)(DWW - 1)) &
                   (vd >= 0.0f) & (vd <= (float)(DHH - 1));

    int xi = (int)fminf(fmaxf(rintf(ud), 0.0f), (float)(DWW - 1));
    int yi = (int)fminf(fmaxf(rintf(vd), 0.0f), (float)(DHH - 1));
    float ds = __ldg(&depth[(slot * DHH + yi) * DWW + xi]);

    bool valid = valid_c & valid_d & (z > 0.0f) & (ds > 0.0f);
    float dist = __fmul_rn(fabsf(__fsub_rn(z, ds)), 16.0f);
    float w  = valid ? __expf(-__fmul_rn(dist, dist)) : 0.0f;
    float vc01 = valid ? 1.0f : 0.0f;
    if (n >= NPTS) { w = 0.0f; vc01 = 0.0f; }

    // wsum/cnt: butterfly within each 8-lane point group
    float wsum = w, cnt = vc01;
#pragma unroll
    for (int d = 1; d < 8; d <<= 1) {
        wsum += __shfl_xor_sync(FULL, wsum, d);
        cnt  += __shfl_xor_sync(FULL, cnt, d);
    }

    // per-(pt,view) bilinear precompute (this lane owns it)
    float ucl = fminf(fmaxf(uc, 0.0f), (float)(FWW - 1));
    float vcl = fminf(fmaxf(vc, 0.0f), (float)(FHH - 1));
    float x0f = floorf(ucl), y0f = floorf(vcl);
    int x0 = (int)x0f, y0 = (int)y0f;
    int x1 = min(x0 + 1, FWW - 1);
    int y1 = min(y0 + 1, FHH - 1);
    float wx = ucl - x0f, wy = vcl - y0f;
    float wq0 = w * (1.0f - wx);
    float wq1 = w * wx;
    int addr00 = (y0 * FWW + x0) * CPH;       // half units
    int dxo = (x1 - x0) * CPH;
    int dyo = (y1 - y0) * FWW * CPH;

    unsigned ball = __ballot_sync(FULL, w != 0.0f);
    unsigned mask8 = (ball >> (grp * 8)) & 0xffu;

    float acc[8];
#pragma unroll
    for (int j = 0; j < 8; j++) acc[j] = 0.0f;

    while (__any_sync(FULL, mask8 != 0u)) {
        bool act = (mask8 != 0u);
        int vvg = act ? (__ffs(mask8) - 1) : 0;
        mask8 &= mask8 - 1;                   // 0 stays 0
        int src = (lane & 24) | vvg;
        float q0  = __shfl_sync(FULL, wq0, src);
        float q1  = __shfl_sync(FULL, wq1, src);
        float wyv = __shfl_sync(FULL, wy, src);
        int a00   = __shfl_sync(FULL, addr00, src);
        int dxv   = __shfl_sync(FULL, dxo, src);
        int dyv   = __shfl_sync(FULL, dyo, src);
        float w00 = q0 * (1.0f - wyv);
        float w01 = q1 * (1.0f - wyv);
        float w10 = q0 * wyv;
        float w11 = q1 * wyv;
        if (act) {
            const __half* fb = g_feats_h + (size_t)vvg * (FHH * FWW * CPH)
                             + a00 + slot * 8;
            uint4 r00 = __ldg(reinterpret_cast<const uint4*>(fb));
            uint4 r01 = __ldg(reinterpret_cast<const uint4*>(fb + dxv));
            uint4 r10 = __ldg(reinterpret_cast<const uint4*>(fb + dyv));
            uint4 r11 = __ldg(reinterpret_cast<const uint4*>(fb + dxv + dyv));
            const __half2* h00 = reinterpret_cast<const __half2*>(&r00);
            const __half2* h01 = reinterpret_cast<const __half2*>(&r01);
            const __half2* h10 = reinterpret_cast<const __half2*>(&r10);
            const __half2* h11 = reinterpret_cast<const __half2*>(&r11);
#pragma unroll
            for (int j = 0; j < 4; j++) {
                float2 f00 = __half22float2(h00[j]);
                float2 f01 = __half22float2(h01[j]);
                float2 f10 = __half22float2(h10[j]);
                float2 f11 = __half22float2(h11[j]);
                acc[2*j+0] += w00*f00.x + w01*f01.x + w10*f10.x + w11*f11.x;
                acc[2*j+1] += w00*f00.y + w01*f01.y + w10*f10.y + w11*f11.y;
            }
        }
    }

    // stage to smem: sacc[pt][channel]; lane owns channels slot*8..slot*8+7
    __shared__ float sacc[PPB][50];
#pragma unroll
    for (int j = 0; j < 8; j++) {
        int c = slot * 8 + j;
        if (c < 49) sacc[pt_local][c] = acc[j];
    }
    if (slot == 0) {
        sacc[pt_local][47] = wsum;
        sacc[pt_local][48] = cnt;
    }
    __syncthreads();

    // coalesced block store: out = density(47,N) | wsum(N) | cnt(N)
    const int base_n = blockIdx.x * PPB;
    for (int t = tid; t < 49 * PPB; t += 256) {
        int c = t >> 5, j = t & 31;
        int nn = base_n + j;
        if (nn < NPTS) out[(size_t)c * NPTS + nn] = sacc[j][c];
    }
}

// ---------------------------------------------------------------------------
extern "C" void kernel_launch(void* const* d_in, const int* in_sizes, int n_in,
                              void* d_out, int out_size) {
    const float* img_feats  = (const float*)d_in[0];   // (1,8,47,60,80)
    const float* pred_depth = (const float*)d_in[1];   // (1,8,240,320)
    const float* poses      = (const float*)d_in[2];   // (1,8,4,4)
    const float* K_color    = (const float*)d_in[3];   // (1,8,3,3)
    const float* K_depth    = (const float*)d_in[4];   // (1,8,3,3)
    const float* coords     = (const float*)d_in[5];   // (1,150000,3)
    float* out = (float*)d_out;

    transpose_feats_kernel<<<BV * FHH, 256>>>(img_feats, poses, K_color, K_depth);
    fuse_kernel<<<(NPTS + PPB - 1) / PPB, 256>>>(coords, pred_depth, out);
}